// round 1
// baseline (speedup 1.0000x reference)
#include <cuda_runtime.h>
#include <math.h>

// Problem dims
#define BB   64
#define NN   49
#define ENC  2048
#define DEC  512
#define ATT  512
#define EMB  300
#define VV   10000
#define TT   30
#define TP1  31
#define CIN  (EMB + ENC + DEC)   // 2860
#define G4   (4 * DEC)           // 2048

// ---------------- scratch (device globals: no allocation allowed) ----------
__device__ float g_uhs[BB * NN * ATT];     // 6.4 MB  u_hs = features @ U_w^T + U_b
__device__ float g_meanf[BB * ENC];
__device__ float g_h[2 * BB * DEC];        // double-buffered h
__device__ float g_c[2 * BB * DEC];        // double-buffered c
__device__ float g_wah[BB * ATT];
__device__ float g_lin[BB * CIN];          // [x(300) | context(2048) | h(512)]
__device__ float g_gates[BB * G4];
__device__ float g_H[BB * TT * DEC];       // h history, row = b*TT + t
__device__ float g_catw[G4 * CIN];         // [ih_w | hh_w] concatenated per row
__device__ float g_catb[G4];

__device__ __forceinline__ float sigmoidf_(float x) { return 1.0f / (1.0f + expf(-x)); }
__device__ __forceinline__ float wred_sum(float v) {
    #pragma unroll
    for (int o = 16; o > 0; o >>= 1) v += __shfl_xor_sync(0xffffffffu, v, o);
    return v;
}

// ---------------- generic SGEMM: C[M,N] = A[M,K] @ B[N,K]^T (+bias) --------
// Split-K via gridDim.z (ATOMIC=true: atomicAdd into zeroed C; bias on z==0).
template <int BM, int BN, int BK, int TM, int TN, bool ATOMIC>
__global__ __launch_bounds__(256) void sgemm_nt(
    const float* __restrict__ A, const float* __restrict__ B,
    const float* __restrict__ bias, float* __restrict__ C,
    int M, int N, int K, int kChunk)
{
    constexpr int THX = BN / TN;           // 16
    constexpr int PAD = 4;
    __shared__ __align__(16) float sA[BK][BM + PAD];
    __shared__ __align__(16) float sB[BK][BN + PAD];

    const int tid = threadIdx.x;
    const int tx  = tid % THX;
    const int ty  = tid / THX;
    const int m0  = blockIdx.y * BM;
    const int n0  = blockIdx.x * BN;
    const int k0  = blockIdx.z * kChunk;
    const int kEnd = min(K, k0 + kChunk);

    float acc[TM][TN];
    #pragma unroll
    for (int i = 0; i < TM; i++)
        #pragma unroll
        for (int j = 0; j < TN; j++) acc[i][j] = 0.0f;

    for (int kk = k0; kk < kEnd; kk += BK) {
        #pragma unroll 4
        for (int i = tid; i < BM * BK; i += 256) {
            int r = i / BK, c = i % BK;
            int gm = m0 + r, gk = kk + c;
            sA[c][r] = (gm < M && gk < kEnd) ? A[(size_t)gm * K + gk] : 0.0f;
        }
        #pragma unroll 4
        for (int i = tid; i < BN * BK; i += 256) {
            int r = i / BK, c = i % BK;
            int gn = n0 + r, gk = kk + c;
            sB[c][r] = (gn < N && gk < kEnd) ? B[(size_t)gn * K + gk] : 0.0f;
        }
        __syncthreads();

        #pragma unroll
        for (int k = 0; k < BK; k++) {
            float af[TM], bf[TN];
            #pragma unroll
            for (int i = 0; i < TM; i += 4) {
                float4 v = *reinterpret_cast<const float4*>(&sA[k][ty * TM + i]);
                af[i] = v.x; af[i+1] = v.y; af[i+2] = v.z; af[i+3] = v.w;
            }
            #pragma unroll
            for (int j = 0; j < TN; j += 4) {
                float4 v = *reinterpret_cast<const float4*>(&sB[k][tx * TN + j]);
                bf[j] = v.x; bf[j+1] = v.y; bf[j+2] = v.z; bf[j+3] = v.w;
            }
            #pragma unroll
            for (int i = 0; i < TM; i++)
                #pragma unroll
                for (int j = 0; j < TN; j++) acc[i][j] = fmaf(af[i], bf[j], acc[i][j]);
        }
        __syncthreads();
    }

    const bool addb = (blockIdx.z == 0) && (bias != nullptr);
    #pragma unroll
    for (int i = 0; i < TM; i++) {
        int gm = m0 + ty * TM + i;
        if (gm >= M) continue;
        #pragma unroll
        for (int j = 0; j < TN; j++) {
            int gn = n0 + tx * TN + j;
            if (gn >= N) continue;
            float v = acc[i][j] + (addb ? bias[gn] : 0.0f);
            if (ATOMIC) atomicAdd(&C[(size_t)gm * N + gn], v);
            else        C[(size_t)gm * N + gn] = v;
        }
    }
}

// ---------------- setup: concat weights, mean features, init h0/c0 ---------
__global__ __launch_bounds__(256) void setup_cat_kernel(
    const float* __restrict__ ih_w, const float* __restrict__ ih_b,
    const float* __restrict__ hh_w, const float* __restrict__ hh_b)
{
    int idx = blockIdx.x * 256 + threadIdx.x;
    int total = G4 * CIN;
    if (idx < total) {
        int j = idx / CIN, k = idx - j * CIN;
        g_catw[idx] = (k < EMB + ENC) ? ih_w[(size_t)j * (EMB + ENC) + k]
                                      : hh_w[(size_t)j * DEC + (k - (EMB + ENC))];
    }
    if (idx < G4) g_catb[idx] = ih_b[idx] + hh_b[idx];
}

__global__ __launch_bounds__(256) void mean_kernel(const float* __restrict__ features)
{
    int b = blockIdx.x;
    for (int e = threadIdx.x; e < ENC; e += 256) {
        float s = 0.0f;
        #pragma unroll 7
        for (int n = 0; n < NN; n++) s += features[((size_t)b * NN + n) * ENC + e];
        g_meanf[b * ENC + e] = s * (1.0f / (float)NN);
    }
}

// warp per (b,d): h0 = meanf @ initH_w^T + b ; c0 likewise
__global__ __launch_bounds__(256) void init_hc_kernel(
    const float* __restrict__ Hw, const float* __restrict__ Hb,
    const float* __restrict__ Cw, const float* __restrict__ Cb)
{
    int w = (blockIdx.x * 256 + threadIdx.x) >> 5;
    int lane = threadIdx.x & 31;
    if (w >= BB * DEC) return;
    int b = w >> 9, d = w & (DEC - 1);
    const float* mf = g_meanf + b * ENC;
    const float* wh = Hw + (size_t)d * ENC;
    const float* wc = Cw + (size_t)d * ENC;
    float sh = 0.0f, sc = 0.0f;
    for (int k = lane; k < ENC; k += 32) {
        float m = mf[k];
        sh = fmaf(m, wh[k], sh);
        sc = fmaf(m, wc[k], sc);
    }
    sh = wred_sum(sh); sc = wred_sum(sc);
    if (lane == 0) {
        g_h[b * DEC + d] = sh + Hb[d];
        g_c[b * DEC + d] = sc + Cb[d];
    }
}

// ---------------- per-step attention: scores -> softmax -> context ---------
// one block per b. Reads g_wah (precomputed h@W_w^T+W_b), writes alphas to
// output and assembles g_lin = [emb(x_t) | context | h].
__global__ __launch_bounds__(256) void attn_kernel(
    const float* __restrict__ h, const float* __restrict__ features,
    const float* __restrict__ emb, const int* __restrict__ captions,
    const float* __restrict__ Aw, const float* __restrict__ Ab,
    float* __restrict__ alphas_out, int t)
{
    int b = blockIdx.x;
    int tid = threadIdx.x;
    int warp = tid >> 5, lane = tid & 31;
    __shared__ float sh_wah[ATT];
    __shared__ float sh_sc[NN];

    for (int k = tid; k < ATT; k += 256) sh_wah[k] = g_wah[b * ATT + k];
    __syncthreads();

    const float ab = Ab[0];
    for (int n = warp; n < NN; n += 8) {
        const float* u = g_uhs + ((size_t)b * NN + n) * ATT;
        float s = 0.0f;
        for (int k = lane; k < ATT; k += 32)
            s = fmaf(Aw[k], tanhf(u[k] + sh_wah[k]), s);
        s = wred_sum(s);
        if (lane == 0) sh_sc[n] = s + ab;
    }
    __syncthreads();

    if (tid < 32) {
        float m = -1e30f;
        for (int n = tid; n < NN; n += 32) m = fmaxf(m, sh_sc[n]);
        #pragma unroll
        for (int o = 16; o > 0; o >>= 1) m = fmaxf(m, __shfl_xor_sync(0xffffffffu, m, o));
        float s = 0.0f;
        for (int n = tid; n < NN; n += 32) { float e = __expf(sh_sc[n] - m); sh_sc[n] = e; s += e; }
        s = wred_sum(s);
        float inv = 1.0f / s;
        for (int n = tid; n < NN; n += 32) sh_sc[n] *= inv;
    }
    __syncthreads();

    // alphas out: [B, T, N]
    for (int n = tid; n < NN; n += 256)
        alphas_out[((size_t)b * TT + t) * NN + n] = sh_sc[n];

    // context -> lin[300:2348]
    float* lin = g_lin + (size_t)b * CIN;
    for (int e = tid; e < ENC; e += 256) {
        float acc = 0.0f;
        const float* f = features + (size_t)b * NN * ENC + e;
        #pragma unroll 7
        for (int n = 0; n < NN; n++) acc = fmaf(sh_sc[n], f[(size_t)n * ENC], acc);
        lin[EMB + e] = acc;
    }
    // x_t -> lin[0:300]
    int cap = captions[b * TP1 + t];
    const float* er = emb + (size_t)cap * EMB;
    for (int k = tid; k < EMB; k += 256) lin[k] = er[k];
    // h -> lin[2348:2860]
    for (int k = tid; k < DEC; k += 256) lin[EMB + ENC + k] = h[b * DEC + k];
}

// ---------------- per-step LSTM pointwise ----------------------------------
__global__ __launch_bounds__(256) void lstm_kernel(
    const float* __restrict__ c_old, float* __restrict__ c_new,
    float* __restrict__ h_new, int t)
{
    int idx = blockIdx.x * 256 + threadIdx.x;   // 0 .. BB*DEC-1
    if (idx >= BB * DEC) return;
    int b = idx >> 9, d = idx & (DEC - 1);
    const float* g = g_gates + (size_t)b * G4;
    float gi = sigmoidf_(g[d]);
    float gf = sigmoidf_(g[DEC + d]);
    float gg = tanhf(g[2 * DEC + d]);
    float go = sigmoidf_(g[3 * DEC + d]);
    float c = fmaf(gf, c_old[idx], gi * gg);
    float h = go * tanhf(c);
    c_new[idx] = c;
    h_new[idx] = h;
    g_H[((size_t)b * TT + t) * DEC + d] = h;
}

// ---------------- host orchestration ---------------------------------------
extern "C" void kernel_launch(void* const* d_in, const int* in_sizes, int n_in,
                              void* d_out, int out_size)
{
    const float* features = (const float*)d_in[0];
    const int*   captions = (const int*)  d_in[1];
    const float* emb      = (const float*)d_in[2];
    const float* U_w      = (const float*)d_in[3];
    const float* U_b      = (const float*)d_in[4];
    const float* W_w      = (const float*)d_in[5];
    const float* W_b      = (const float*)d_in[6];
    const float* A_w      = (const float*)d_in[7];
    const float* A_b      = (const float*)d_in[8];
    const float* initH_w  = (const float*)d_in[9];
    const float* initH_b  = (const float*)d_in[10];
    const float* initC_w  = (const float*)d_in[11];
    const float* initC_b  = (const float*)d_in[12];
    const float* ih_w     = (const float*)d_in[13];
    const float* ih_b     = (const float*)d_in[14];
    const float* hh_w     = (const float*)d_in[15];
    const float* hh_b     = (const float*)d_in[16];
    const float* fcn_w    = (const float*)d_in[17];
    const float* fcn_b    = (const float*)d_in[18];

    float* preds  = (float*)d_out;                       // [64,30,10000]
    float* alphas = (float*)d_out + (size_t)BB * TT * VV; // [64,30,49]

    float *p_uhs, *p_h, *p_c, *p_wah, *p_lin, *p_gates, *p_H, *p_catw, *p_catb;
    cudaGetSymbolAddress((void**)&p_uhs,   g_uhs);
    cudaGetSymbolAddress((void**)&p_h,     g_h);
    cudaGetSymbolAddress((void**)&p_c,     g_c);
    cudaGetSymbolAddress((void**)&p_wah,   g_wah);
    cudaGetSymbolAddress((void**)&p_lin,   g_lin);
    cudaGetSymbolAddress((void**)&p_gates, g_gates);
    cudaGetSymbolAddress((void**)&p_H,     g_H);
    cudaGetSymbolAddress((void**)&p_catw,  g_catw);
    cudaGetSymbolAddress((void**)&p_catb,  g_catb);

    const int HSZ = BB * DEC;

    // one-time (per launch) prep
    setup_cat_kernel<<<(G4 * CIN + 255) / 256, 256>>>(ih_w, ih_b, hh_w, hh_b);
    mean_kernel<<<BB, 256>>>(features);
    init_hc_kernel<<<(BB * DEC) / 8, 256>>>(initH_w, initH_b, initC_w, initC_b);

    // u_hs = features @ U_w^T + U_b   [3136, 512]
    sgemm_nt<128, 128, 16, 8, 8, false><<<dim3(4, 25, 1), 256>>>(
        features, U_w, U_b, p_uhs, BB * NN, ATT, ENC, ENC);

    for (int t = 0; t < TT; t++) {
        int cur = t & 1, nxt = cur ^ 1;
        // w_ah = h @ W_w^T + W_b  (split-K, atomic)
        cudaMemsetAsync(p_wah, 0, (size_t)BB * ATT * sizeof(float));
        sgemm_nt<64, 64, 16, 4, 4, true><<<dim3(8, 1, 8), 256>>>(
            p_h + cur * HSZ, W_w, W_b, p_wah, BB, ATT, DEC, DEC / 8);

        attn_kernel<<<BB, 256>>>(p_h + cur * HSZ, features, emb, captions,
                                 A_w, A_b, alphas, t);

        // gates = lin @ catw^T + catb  (split-K, atomic)
        cudaMemsetAsync(p_gates, 0, (size_t)BB * G4 * sizeof(float));
        sgemm_nt<64, 64, 16, 4, 4, true><<<dim3(G4 / 64, 1, 20), 256>>>(
            p_lin, p_catw, p_catb, p_gates, BB, G4, CIN, CIN / 20);

        lstm_kernel<<<(BB * DEC + 255) / 256, 256>>>(
            p_c + cur * HSZ, p_c + nxt * HSZ, p_h + nxt * HSZ, t);
    }

    // preds = H @ fcn_w^T + fcn_b   [1920, 10000], row = b*30+t maps to output
    sgemm_nt<128, 128, 16, 8, 8, false><<<dim3((VV + 127) / 128, (BB * TT) / 128, 1), 256>>>(
        p_H, fcn_w, fcn_b, preds, BB * TT, VV, DEC, DEC);
}